// round 14
// baseline (speedup 1.0000x reference)
#include <cuda_runtime.h>
#include <cuda_bf16.h>
#include <cstdint>

#define CIN   256
#define HD    512
#define NHEAD 4
#define DDIM  128

// Head-averaged weight, split into bf16 hi/lo, stored [n][k] row-major (B^T)
__device__ __align__(16) unsigned short g_Wt_hi[DDIM * CIN];
__device__ __align__(16) unsigned short g_Wt_lo[DDIM * CIN];
__device__ __align__(16) float g_bias[DDIM];

#define SW128(x) ((x) ^ (((x) >> 3) & 0x70))

// SMEM layout (bytes)
#define SM_BIAS  0
#define SM_A     1024                        // 2 bufs x (hi 16K, lo 16K)
#define SM_B     (1024 + 4 * 16384)          // Bh[128][264], Bl[128][264]
#define BSTRIDE  528
#define BSIZE    (128 * BSTRIDE)
#define SMEM_SZ  (SM_B + 2 * BSIZE)

__device__ __forceinline__ uint32_t smem_u32(const void* p) {
    uint32_t a;
    asm("{ .reg .u64 t; cvta.to.shared.u64 t, %1; cvt.u32.u64 %0, t; }" : "=r"(a) : "l"(p));
    return a;
}
__device__ __forceinline__ void ldmatrix_x4(uint32_t* r, uint32_t addr) {
    asm volatile("ldmatrix.sync.aligned.m8n8.x4.shared.b16 {%0,%1,%2,%3}, [%4];"
                 : "=r"(r[0]), "=r"(r[1]), "=r"(r[2]), "=r"(r[3]) : "r"(addr));
}
__device__ __forceinline__ void mma_bf16(float* c, const uint32_t* a, const uint32_t* b) {
    asm volatile(
        "mma.sync.aligned.m16n8k16.row.col.f32.bf16.bf16.f32 "
        "{%0,%1,%2,%3}, {%4,%5,%6,%7}, {%8,%9}, {%0,%1,%2,%3};"
        : "+f"(c[0]), "+f"(c[1]), "+f"(c[2]), "+f"(c[3])
        : "r"(a[0]), "r"(a[1]), "r"(a[2]), "r"(a[3]), "r"(b[0]), "r"(b[1]));
}

// ---------------------------------------------------------------------------
// Prologue: W̄[k][n] = 0.25*sum_h Wv[k, h*128+n] → bf16 hi/lo at [n][k]; bias.
// ---------------------------------------------------------------------------
__global__ void reduce_weights(const float* __restrict__ Wv, const float* __restrict__ bv)
{
    int idx = blockIdx.x * blockDim.x + threadIdx.x;
    if (idx < DDIM * CIN) {
        int n = idx >> 8;
        int k = idx & 255;
        float s = 0.f;
#pragma unroll
        for (int h = 0; h < NHEAD; h++) s += Wv[(size_t)k * HD + h * DDIM + n];
        float w = 0.25f * s;
        __nv_bfloat16 hh = __float2bfloat16_rn(w);
        float res = w - __bfloat162float(hh);
        __nv_bfloat16 ll = __float2bfloat16_rn(res);
        unsigned short uh, ul;
        memcpy(&uh, &hh, 2); memcpy(&ul, &ll, 2);
        g_Wt_hi[n * CIN + k] = uh;
        g_Wt_lo[n * CIN + k] = ul;
    }
    if (idx < DDIM) {
        float s = 0.f;
#pragma unroll
        for (int h = 0; h < NHEAD; h++) s += bv[h * DDIM + idx];
        g_bias[idx] = 0.25f * s;
    }
}

// ---------------------------------------------------------------------------
// out[N,128] = A[N,256] @ W̄ + bias   (HMMA bf16 3-term split)
// ---------------------------------------------------------------------------
__global__ __launch_bounds__(256, 1) void gemm_hmma(const float* __restrict__ A,
                                                    float* __restrict__ out, int N)
{
    extern __shared__ __align__(1024) char smem[];
    const uint32_t sb = smem_u32(smem);
    const int t = threadIdx.x;
    const int wid = t >> 5, lane = t & 31;
    const int r0 = blockIdx.x * 128;

    const int m0 = (wid & 3) * 32;     // warp row base within CTA tile
    const int n0 = (wid >> 2) * 64;    // warp col base

    // per-lane ldmatrix address components
    const uint32_t mA_local = ((lane >> 3) & 1) * 8 + (lane & 7);
    const uint32_t kA_off   = (lane >> 4) * 16;               // bytes
    const uint32_t nB_local = (lane >> 4) * 8 + (lane & 7);
    const uint32_t kB_off   = ((lane >> 3) & 1) * 16;         // bytes

    // ---- stage bias + full B (hi/lo) into smem ----
    if (t < 128) *reinterpret_cast<float*>(smem + SM_BIAS + t * 4) = g_bias[t];
#pragma unroll
    for (int i = 0; i < 16; i++) {
        int idx = i * 256 + t;            // 0..4095 uint4 units per array
        int row = idx >> 5;               // n
        int u = idx & 31;                 // 16-B unit within 512-B of data
        uint4 vh = *reinterpret_cast<const uint4*>(g_Wt_hi + row * CIN + u * 8);
        uint4 vl = *reinterpret_cast<const uint4*>(g_Wt_lo + row * CIN + u * 8);
        *reinterpret_cast<uint4*>(smem + SM_B + row * BSTRIDE + u * 16) = vh;
        *reinterpret_cast<uint4*>(smem + SM_B + BSIZE + row * BSTRIDE + u * 16) = vl;
    }

    float acc[2][8][4];
#pragma unroll
    for (int mt = 0; mt < 2; mt++)
#pragma unroll
        for (int nt = 0; nt < 8; nt++)
#pragma unroll
            for (int r = 0; r < 4; r++) acc[mt][nt][r] = 0.f;

    float4 pf[8];
    // ---- prefetch chunk 0 ----
#pragma unroll
    for (int it = 0; it < 8; it++) {
        int v = it * 256 + t;
        int row = v >> 4, u = v & 15;
        int grow = r0 + row;
        pf[it] = (grow < N)
            ? *reinterpret_cast<const float4*>(A + (size_t)grow * CIN + u * 4)
            : make_float4(0.f, 0.f, 0.f, 0.f);
    }
    // ---- convert/store chunk 0 into buf 0 ----
    {
        uint32_t ah = sb + SM_A;            // buf0 hi
        uint32_t al = ah + 16384;
#pragma unroll
        for (int it = 0; it < 8; it++) {
            int v = it * 256 + t;
            int row = v >> 4, u = v & 15;
            float4 f = pf[it];
            __nv_bfloat16 h0 = __float2bfloat16_rn(f.x), h1 = __float2bfloat16_rn(f.y);
            __nv_bfloat16 h2 = __float2bfloat16_rn(f.z), h3 = __float2bfloat16_rn(f.w);
            __nv_bfloat16 l0 = __float2bfloat16_rn(f.x - __bfloat162float(h0));
            __nv_bfloat16 l1 = __float2bfloat16_rn(f.y - __bfloat162float(h1));
            __nv_bfloat16 l2 = __float2bfloat16_rn(f.z - __bfloat162float(h2));
            __nv_bfloat16 l3 = __float2bfloat16_rn(f.w - __bfloat162float(h3));
            unsigned short s0, s1, s2, s3, q0, q1, q2, q3;
            memcpy(&s0, &h0, 2); memcpy(&s1, &h1, 2); memcpy(&s2, &h2, 2); memcpy(&s3, &h3, 2);
            memcpy(&q0, &l0, 2); memcpy(&q1, &l1, 2); memcpy(&q2, &l2, 2); memcpy(&q3, &l3, 2);
            uint32_t hx = (uint32_t)s0 | ((uint32_t)s1 << 16);
            uint32_t hy = (uint32_t)s2 | ((uint32_t)s3 << 16);
            uint32_t lx = (uint32_t)q0 | ((uint32_t)q1 << 16);
            uint32_t ly = (uint32_t)q2 | ((uint32_t)q3 << 16);
            uint32_t off = SW128((uint32_t)(row * 128 + u * 8));
            asm volatile("st.shared.v2.b32 [%0], {%1,%2};" :: "r"(ah + off), "r"(hx), "r"(hy) : "memory");
            asm volatile("st.shared.v2.b32 [%0], {%1,%2};" :: "r"(al + off), "r"(lx), "r"(ly) : "memory");
        }
    }
    __syncthreads();

    // ---- main loop over 4 K-chunks of 64 ----
#pragma unroll 1
    for (int c = 0; c < 4; c++) {
        const int buf = c & 1;
        // prefetch next chunk while MMAs run
        if (c < 3) {
#pragma unroll
            for (int it = 0; it < 8; it++) {
                int v = it * 256 + t;
                int row = v >> 4, u = v & 15;
                int grow = r0 + row;
                pf[it] = (grow < N)
                    ? *reinterpret_cast<const float4*>(A + (size_t)grow * CIN + (c + 1) * 64 + u * 4)
                    : make_float4(0.f, 0.f, 0.f, 0.f);
            }
        }

        const uint32_t abh = sb + SM_A + buf * 32768;          // A hi
        const uint32_t abl = abh + 16384;                      // A lo
#pragma unroll 1
        for (int split = 0; split < 3; split++) {
            const uint32_t abase = (split == 2) ? abl : abh;
            const uint32_t bbase = sb + SM_B + ((split == 1) ? BSIZE : 0);
#pragma unroll
            for (int k16 = 0; k16 < 4; k16++) {
                uint32_t a[2][4];
#pragma unroll
                for (int mt = 0; mt < 2; mt++) {
                    uint32_t row = m0 + mt * 16 + mA_local;
                    uint32_t off = SW128(row * 128 + (uint32_t)k16 * 32 + kA_off);
                    ldmatrix_x4(a[mt], abase + off);
                }
                uint32_t b[8][2];
#pragma unroll
                for (int nq = 0; nq < 4; nq++) {
                    uint32_t r[4];
                    uint32_t nrow = n0 + nq * 16 + nB_local;
                    uint32_t addr = bbase + nrow * BSTRIDE + (uint32_t)c * 128 + (uint32_t)k16 * 32 + kB_off;
                    ldmatrix_x4(r, addr);
                    b[nq * 2 + 0][0] = r[0]; b[nq * 2 + 0][1] = r[1];
                    b[nq * 2 + 1][0] = r[2]; b[nq * 2 + 1][1] = r[3];
                }
#pragma unroll
                for (int mt = 0; mt < 2; mt++)
#pragma unroll
                    for (int nt = 0; nt < 8; nt++)
                        mma_bf16(acc[mt][nt], a[mt], b[nt]);
            }
        }

        // convert + store prefetched chunk into the other buffer
        if (c < 3) {
            uint32_t ah = sb + SM_A + ((c + 1) & 1) * 32768;
            uint32_t al = ah + 16384;
#pragma unroll
            for (int it = 0; it < 8; it++) {
                int v = it * 256 + t;
                int row = v >> 4, u = v & 15;
                float4 f = pf[it];
                __nv_bfloat16 h0 = __float2bfloat16_rn(f.x), h1 = __float2bfloat16_rn(f.y);
                __nv_bfloat16 h2 = __float2bfloat16_rn(f.z), h3 = __float2bfloat16_rn(f.w);
                __nv_bfloat16 l0 = __float2bfloat16_rn(f.x - __bfloat162float(h0));
                __nv_bfloat16 l1 = __float2bfloat16_rn(f.y - __bfloat162float(h1));
                __nv_bfloat16 l2 = __float2bfloat16_rn(f.z - __bfloat162float(h2));
                __nv_bfloat16 l3 = __float2bfloat16_rn(f.w - __bfloat162float(h3));
                unsigned short s0, s1, s2, s3, q0, q1, q2, q3;
                memcpy(&s0, &h0, 2); memcpy(&s1, &h1, 2); memcpy(&s2, &h2, 2); memcpy(&s3, &h3, 2);
                memcpy(&q0, &l0, 2); memcpy(&q1, &l1, 2); memcpy(&q2, &l2, 2); memcpy(&q3, &l3, 2);
                uint32_t hx = (uint32_t)s0 | ((uint32_t)s1 << 16);
                uint32_t hy = (uint32_t)s2 | ((uint32_t)s3 << 16);
                uint32_t lx = (uint32_t)q0 | ((uint32_t)q1 << 16);
                uint32_t ly = (uint32_t)q2 | ((uint32_t)q3 << 16);
                uint32_t off = SW128((uint32_t)(row * 128 + u * 8));
                asm volatile("st.shared.v2.b32 [%0], {%1,%2};" :: "r"(ah + off), "r"(hx), "r"(hy) : "memory");
                asm volatile("st.shared.v2.b32 [%0], {%1,%2};" :: "r"(al + off), "r"(lx), "r"(ly) : "memory");
            }
        }
        __syncthreads();
    }

    // ---- epilogue: + bias, store ----
    const float* bias = reinterpret_cast<const float*>(smem + SM_BIAS);
#pragma unroll
    for (int mt = 0; mt < 2; mt++) {
        int row_lo = r0 + m0 + mt * 16 + (lane >> 2);
        int row_hi = row_lo + 8;
#pragma unroll
        for (int nt = 0; nt < 8; nt++) {
            int col = n0 + nt * 8 + (lane & 3) * 2;
            float2 b2 = *reinterpret_cast<const float2*>(bias + col);
            if (row_lo < N) {
                float2 o = make_float2(acc[mt][nt][0] + b2.x, acc[mt][nt][1] + b2.y);
                *reinterpret_cast<float2*>(out + (size_t)row_lo * DDIM + col) = o;
            }
            if (row_hi < N) {
                float2 o = make_float2(acc[mt][nt][2] + b2.x, acc[mt][nt][3] + b2.y);
                *reinterpret_cast<float2*>(out + (size_t)row_hi * DDIM + col) = o;
            }
        }
    }
}

// ---------------------------------------------------------------------------
extern "C" void kernel_launch(void* const* d_in, const int* in_sizes, int n_in,
                              void* d_out, int out_size)
{
    const float* v_in = (const float*)d_in[2];
    const float* Wv   = (const float*)d_in[7];
    const float* bv   = (const float*)d_in[8];
    float* out = (float*)d_out;

    const int N = in_sizes[0] / CIN;
    const int rowBlocks = (N + 127) / 128;

    cudaFuncSetAttribute(gemm_hmma, cudaFuncAttributeMaxDynamicSharedMemorySize, SMEM_SZ);

    reduce_weights<<<(DDIM * CIN + 255) / 256, 256>>>(Wv, bv);
    gemm_hmma<<<rowBlocks, 256, SMEM_SZ>>>(v_in, out, N);
}

// round 15
// speedup vs baseline: 1.0030x; 1.0030x over previous
#include <cuda_runtime.h>
#include <cuda_bf16.h>
#include <cstdint>

#define CIN   256
#define HD    512
#define NHEAD 4
#define DDIM  128

// Head-averaged weight, split into bf16 hi/lo, stored [n][k] row-major (B^T)
__device__ __align__(16) unsigned short g_Wt_hi[DDIM * CIN];
__device__ __align__(16) unsigned short g_Wt_lo[DDIM * CIN];
__device__ __align__(16) float g_bias[DDIM];

#define SW128(x) ((x) ^ (((x) >> 3) & 0x70))

// SMEM layout (bytes)
#define SM_BIAS  0
#define SM_A     1024                        // 2 bufs x (hi 16K, lo 16K)
#define SM_B     (1024 + 4 * 16384)          // Bh[128][264], Bl[128][264]
#define BSTRIDE  528
#define BSIZE    (128 * BSTRIDE)
#define SMEM_SZ  (SM_B + 2 * BSIZE)

__device__ __forceinline__ uint32_t smem_u32(const void* p) {
    uint32_t a;
    asm("{ .reg .u64 t; cvta.to.shared.u64 t, %1; cvt.u32.u64 %0, t; }" : "=r"(a) : "l"(p));
    return a;
}
__device__ __forceinline__ void ldmatrix_x4(uint32_t* r, uint32_t addr) {
    asm volatile("ldmatrix.sync.aligned.m8n8.x4.shared.b16 {%0,%1,%2,%3}, [%4];"
                 : "=r"(r[0]), "=r"(r[1]), "=r"(r[2]), "=r"(r[3]) : "r"(addr));
}
__device__ __forceinline__ void mma_bf16(float* c, const uint32_t* a, const uint32_t* b) {
    asm volatile(
        "mma.sync.aligned.m16n8k16.row.col.f32.bf16.bf16.f32 "
        "{%0,%1,%2,%3}, {%4,%5,%6,%7}, {%8,%9}, {%0,%1,%2,%3};"
        : "+f"(c[0]), "+f"(c[1]), "+f"(c[2]), "+f"(c[3])
        : "r"(a[0]), "r"(a[1]), "r"(a[2]), "r"(a[3]), "r"(b[0]), "r"(b[1]));
}

// ---------------------------------------------------------------------------
// Prologue: W̄[k][n] = 0.25*sum_h Wv[k, h*128+n] → bf16 hi/lo at [n][k]; bias.
// ---------------------------------------------------------------------------
__global__ void reduce_weights(const float* __restrict__ Wv, const float* __restrict__ bv)
{
    int idx = blockIdx.x * blockDim.x + threadIdx.x;
    if (idx < DDIM * CIN) {
        int n = idx >> 8;
        int k = idx & 255;
        float s = 0.f;
#pragma unroll
        for (int h = 0; h < NHEAD; h++) s += Wv[(size_t)k * HD + h * DDIM + n];
        float w = 0.25f * s;
        __nv_bfloat16 hh = __float2bfloat16_rn(w);
        float res = w - __bfloat162float(hh);
        __nv_bfloat16 ll = __float2bfloat16_rn(res);
        unsigned short uh, ul;
        memcpy(&uh, &hh, 2); memcpy(&ul, &ll, 2);
        g_Wt_hi[n * CIN + k] = uh;
        g_Wt_lo[n * CIN + k] = ul;
    }
    if (idx < DDIM) {
        float s = 0.f;
#pragma unroll
        for (int h = 0; h < NHEAD; h++) s += bv[h * DDIM + idx];
        g_bias[idx] = 0.25f * s;
    }
}

// ---------------------------------------------------------------------------
// out[N,128] = A[N,256] @ W̄ + bias   (HMMA bf16 3-term split)
// ---------------------------------------------------------------------------
__global__ __launch_bounds__(256, 1) void gemm_hmma(const float* __restrict__ A,
                                                    float* __restrict__ out, int N)
{
    extern __shared__ __align__(1024) char smem[];
    const uint32_t sb = smem_u32(smem);
    const int t = threadIdx.x;
    const int wid = t >> 5, lane = t & 31;
    const int r0 = blockIdx.x * 128;

    const int m0 = (wid & 3) * 32;     // warp row base within CTA tile
    const int n0 = (wid >> 2) * 64;    // warp col base

    // per-lane ldmatrix address components
    const uint32_t mA_local = ((lane >> 3) & 1) * 8 + (lane & 7);
    const uint32_t kA_off   = (lane >> 4) * 16;               // bytes
    const uint32_t nB_local = (lane >> 4) * 8 + (lane & 7);
    const uint32_t kB_off   = ((lane >> 3) & 1) * 16;         // bytes

    // ---- stage bias + full B (hi/lo) into smem ----
    if (t < 128) *reinterpret_cast<float*>(smem + SM_BIAS + t * 4) = g_bias[t];
#pragma unroll
    for (int i = 0; i < 16; i++) {
        int idx = i * 256 + t;            // 0..4095 uint4 units per array
        int row = idx >> 5;               // n
        int u = idx & 31;                 // 16-B unit within 512-B of data
        uint4 vh = *reinterpret_cast<const uint4*>(g_Wt_hi + row * CIN + u * 8);
        uint4 vl = *reinterpret_cast<const uint4*>(g_Wt_lo + row * CIN + u * 8);
        *reinterpret_cast<uint4*>(smem + SM_B + row * BSTRIDE + u * 16) = vh;
        *reinterpret_cast<uint4*>(smem + SM_B + BSIZE + row * BSTRIDE + u * 16) = vl;
    }

    float acc[2][8][4];
#pragma unroll
    for (int mt = 0; mt < 2; mt++)
#pragma unroll
        for (int nt = 0; nt < 8; nt++)
#pragma unroll
            for (int r = 0; r < 4; r++) acc[mt][nt][r] = 0.f;

    float4 pf[8];
    // ---- prefetch chunk 0 ----
#pragma unroll
    for (int it = 0; it < 8; it++) {
        int v = it * 256 + t;
        int row = v >> 4, u = v & 15;
        int grow = r0 + row;
        pf[it] = (grow < N)
            ? *reinterpret_cast<const float4*>(A + (size_t)grow * CIN + u * 4)
            : make_float4(0.f, 0.f, 0.f, 0.f);
    }
    // ---- convert/store chunk 0 into buf 0 ----
    {
        uint32_t ah = sb + SM_A;            // buf0 hi
        uint32_t al = ah + 16384;
#pragma unroll
        for (int it = 0; it < 8; it++) {
            int v = it * 256 + t;
            int row = v >> 4, u = v & 15;
            float4 f = pf[it];
            __nv_bfloat16 h0 = __float2bfloat16_rn(f.x), h1 = __float2bfloat16_rn(f.y);
            __nv_bfloat16 h2 = __float2bfloat16_rn(f.z), h3 = __float2bfloat16_rn(f.w);
            __nv_bfloat16 l0 = __float2bfloat16_rn(f.x - __bfloat162float(h0));
            __nv_bfloat16 l1 = __float2bfloat16_rn(f.y - __bfloat162float(h1));
            __nv_bfloat16 l2 = __float2bfloat16_rn(f.z - __bfloat162float(h2));
            __nv_bfloat16 l3 = __float2bfloat16_rn(f.w - __bfloat162float(h3));
            unsigned short s0, s1, s2, s3, q0, q1, q2, q3;
            memcpy(&s0, &h0, 2); memcpy(&s1, &h1, 2); memcpy(&s2, &h2, 2); memcpy(&s3, &h3, 2);
            memcpy(&q0, &l0, 2); memcpy(&q1, &l1, 2); memcpy(&q2, &l2, 2); memcpy(&q3, &l3, 2);
            uint32_t hx = (uint32_t)s0 | ((uint32_t)s1 << 16);
            uint32_t hy = (uint32_t)s2 | ((uint32_t)s3 << 16);
            uint32_t lx = (uint32_t)q0 | ((uint32_t)q1 << 16);
            uint32_t ly = (uint32_t)q2 | ((uint32_t)q3 << 16);
            uint32_t off = SW128((uint32_t)(row * 128 + u * 8));
            asm volatile("st.shared.v2.b32 [%0], {%1,%2};" :: "r"(ah + off), "r"(hx), "r"(hy) : "memory");
            asm volatile("st.shared.v2.b32 [%0], {%1,%2};" :: "r"(al + off), "r"(lx), "r"(ly) : "memory");
        }
    }
    __syncthreads();

    // ---- main loop over 4 K-chunks of 64 ----
#pragma unroll 1
    for (int c = 0; c < 4; c++) {
        const int buf = c & 1;
        // prefetch next chunk while MMAs run
        if (c < 3) {
#pragma unroll
            for (int it = 0; it < 8; it++) {
                int v = it * 256 + t;
                int row = v >> 4, u = v & 15;
                int grow = r0 + row;
                pf[it] = (grow < N)
                    ? *reinterpret_cast<const float4*>(A + (size_t)grow * CIN + (c + 1) * 64 + u * 4)
                    : make_float4(0.f, 0.f, 0.f, 0.f);
            }
        }

        const uint32_t abh = sb + SM_A + buf * 32768;          // A hi
        const uint32_t abl = abh + 16384;                      // A lo
#pragma unroll 1
        for (int split = 0; split < 3; split++) {
            const uint32_t abase = (split == 2) ? abl : abh;
            const uint32_t bbase = sb + SM_B + ((split == 1) ? BSIZE : 0);
#pragma unroll
            for (int k16 = 0; k16 < 4; k16++) {
                uint32_t a[2][4];
#pragma unroll
                for (int mt = 0; mt < 2; mt++) {
                    uint32_t row = m0 + mt * 16 + mA_local;
                    uint32_t off = SW128(row * 128 + (uint32_t)k16 * 32 + kA_off);
                    ldmatrix_x4(a[mt], abase + off);
                }
                uint32_t b[8][2];
#pragma unroll
                for (int nq = 0; nq < 4; nq++) {
                    uint32_t r[4];
                    uint32_t nrow = n0 + nq * 16 + nB_local;
                    uint32_t addr = bbase + nrow * BSTRIDE + (uint32_t)c * 128 + (uint32_t)k16 * 32 + kB_off;
                    ldmatrix_x4(r, addr);
                    b[nq * 2 + 0][0] = r[0]; b[nq * 2 + 0][1] = r[1];
                    b[nq * 2 + 1][0] = r[2]; b[nq * 2 + 1][1] = r[3];
                }
#pragma unroll
                for (int mt = 0; mt < 2; mt++)
#pragma unroll
                    for (int nt = 0; nt < 8; nt++)
                        mma_bf16(acc[mt][nt], a[mt], b[nt]);
            }
        }

        // convert + store prefetched chunk into the other buffer
        if (c < 3) {
            uint32_t ah = sb + SM_A + ((c + 1) & 1) * 32768;
            uint32_t al = ah + 16384;
#pragma unroll
            for (int it = 0; it < 8; it++) {
                int v = it * 256 + t;
                int row = v >> 4, u = v & 15;
                float4 f = pf[it];
                __nv_bfloat16 h0 = __float2bfloat16_rn(f.x), h1 = __float2bfloat16_rn(f.y);
                __nv_bfloat16 h2 = __float2bfloat16_rn(f.z), h3 = __float2bfloat16_rn(f.w);
                __nv_bfloat16 l0 = __float2bfloat16_rn(f.x - __bfloat162float(h0));
                __nv_bfloat16 l1 = __float2bfloat16_rn(f.y - __bfloat162float(h1));
                __nv_bfloat16 l2 = __float2bfloat16_rn(f.z - __bfloat162float(h2));
                __nv_bfloat16 l3 = __float2bfloat16_rn(f.w - __bfloat162float(h3));
                unsigned short s0, s1, s2, s3, q0, q1, q2, q3;
                memcpy(&s0, &h0, 2); memcpy(&s1, &h1, 2); memcpy(&s2, &h2, 2); memcpy(&s3, &h3, 2);
                memcpy(&q0, &l0, 2); memcpy(&q1, &l1, 2); memcpy(&q2, &l2, 2); memcpy(&q3, &l3, 2);
                uint32_t hx = (uint32_t)s0 | ((uint32_t)s1 << 16);
                uint32_t hy = (uint32_t)s2 | ((uint32_t)s3 << 16);
                uint32_t lx = (uint32_t)q0 | ((uint32_t)q1 << 16);
                uint32_t ly = (uint32_t)q2 | ((uint32_t)q3 << 16);
                uint32_t off = SW128((uint32_t)(row * 128 + u * 8));
                asm volatile("st.shared.v2.b32 [%0], {%1,%2};" :: "r"(ah + off), "r"(hx), "r"(hy) : "memory");
                asm volatile("st.shared.v2.b32 [%0], {%1,%2};" :: "r"(al + off), "r"(lx), "r"(ly) : "memory");
            }
        }
        __syncthreads();
    }

    // ---- epilogue: + bias, store ----
    const float* bias = reinterpret_cast<const float*>(smem + SM_BIAS);
#pragma unroll
    for (int mt = 0; mt < 2; mt++) {
        int row_lo = r0 + m0 + mt * 16 + (lane >> 2);
        int row_hi = row_lo + 8;
#pragma unroll
        for (int nt = 0; nt < 8; nt++) {
            int col = n0 + nt * 8 + (lane & 3) * 2;
            float2 b2 = *reinterpret_cast<const float2*>(bias + col);
            if (row_lo < N) {
                float2 o = make_float2(acc[mt][nt][0] + b2.x, acc[mt][nt][1] + b2.y);
                *reinterpret_cast<float2*>(out + (size_t)row_lo * DDIM + col) = o;
            }
            if (row_hi < N) {
                float2 o = make_float2(acc[mt][nt][2] + b2.x, acc[mt][nt][3] + b2.y);
                *reinterpret_cast<float2*>(out + (size_t)row_hi * DDIM + col) = o;
            }
        }
    }
}

// ---------------------------------------------------------------------------
extern "C" void kernel_launch(void* const* d_in, const int* in_sizes, int n_in,
                              void* d_out, int out_size)
{
    const float* v_in = (const float*)d_in[2];
    const float* Wv   = (const float*)d_in[7];
    const float* bv   = (const float*)d_in[8];
    float* out = (float*)d_out;

    const int N = in_sizes[0] / CIN;
    const int rowBlocks = (N + 127) / 128;

    cudaFuncSetAttribute(gemm_hmma, cudaFuncAttributeMaxDynamicSharedMemorySize, SMEM_SZ);

    reduce_weights<<<(DDIM * CIN + 255) / 256, 256>>>(Wv, bv);
    gemm_hmma<<<rowBlocks, 256, SMEM_SZ>>>(v_in, out, N);
}